// round 2
// baseline (speedup 1.0000x reference)
#include <cuda_runtime.h>
#include <math.h>

// Problem constants
#define SS   8
#define CC   256
#define HH   23
#define WW   23
#define NFLT 529            // number of filters = H*W
#define PP   529            // spatial positions
#define PSTR 532            // padded row stride for residuals (multiple of 4)
#define CKD  2304           // C * 3 * 3
#define DHW  45             // 2H-1

// Scratch (device globals; no allocation allowed)
__device__ float g_f[SS * NFLT * CKD];       // updated filter between iterations
__device__ float g_grad[SS * NFLT * CKD];    // filter gradient
__device__ float g_resid[SS * NFLT * PSTR];  // mapped residuals (padded rows)
__device__ float g_wm[SS * NFLT * PSTR];     // spatial_weight * score_mask
__device__ float g_num[SS * NFLT];           // alpha numerator per (s,nf)
__device__ float g_den[SS * NFLT];           // alpha denominator partial per (s,nf)
__device__ float g_lbl[DHW * DHW];           // label_full table
__device__ float g_sp[DHW * DHW];            // spatial_full table

// ---------------------------------------------------------------------------
// Precompute 45x45 label/spatial tables from w_label / w_spatial
// label(dist) = sum_k w[k] * bin_k(dist), bins are triangular (last clipped)
// ---------------------------------------------------------------------------
__global__ void k_tables(const float* __restrict__ wl, const float* __restrict__ ws) {
    int i = blockIdx.x * blockDim.x + threadIdx.x;
    if (i >= DHW * DHW) return;
    int a = i / DHW, b = i - a * DHW;
    float da = (float)a - 22.0f, db = (float)b - 22.0f;
    float t = sqrtf(da * da + db * db) * 2.0f;  // dist / BIN_DISP(0.5)
    float lab = 0.0f, sp = 0.0f;
#pragma unroll
    for (int k = 0; k < 9; k++) {
        float v = fmaxf(0.0f, 1.0f - fabsf(t - (float)k));
        lab += wl[k] * v;
        sp  += ws[k] * v;
    }
    float v9 = fminf(fmaxf(t - 8.0f, 0.0f), 1.0f);  // clip(1 + (t-9), 0, 1)
    lab += wl[9] * v9;
    sp  += ws[9] * v9;
    g_lbl[i] = lab;
    g_sp[i]  = sp;
}

__global__ void k_zero() {
    int i = blockIdx.x * blockDim.x + threadIdx.x;
    if (i < SS * NFLT) { g_num[i] = 0.0f; g_den[i] = 0.0f; }
}

// ---------------------------------------------------------------------------
// Forward conv as GEMM: out[m=nf, p=(y,x)] = sum_{ck} A[m,ck] * im2col(feat)[ck,p]
// MODE 0: A = filter; epilogue computes mapped residuals + weight-mask
// MODE 1: A = filter_grad; epilogue computes weighted-square row sums -> g_den
// grid: (9, 9, 8) = (Ntiles, Mtiles, S); 256 threads; 64x64x32 tiles, 4x4/thread
// ---------------------------------------------------------------------------
template <int MODE>
__global__ __launch_bounds__(256) void k_fwd(const float* __restrict__ A,
                                             const float* __restrict__ feat) {
    __shared__ float As[32][64];
    __shared__ float Bs[32][64];
    __shared__ float red[64];

    const int s  = blockIdx.z;
    const int m0 = blockIdx.y * 64;
    const int n0 = blockIdx.x * 64;
    const int tid = threadIdx.x;
    const int tx = tid & 15, ty = tid >> 4;

    const float* Ag = A    + (size_t)s * NFLT * CKD;
    const float* Fg = feat + (size_t)s * CC * HH * WW;

    float acc[4][4] = {};

    for (int k0 = 0; k0 < CKD; k0 += 32) {
        // A tile 64x32, vectorized float4, transposed into As[k][m]
#pragma unroll
        for (int q = 0; q < 2; q++) {
            int idx = tid + q * 256;     // 0..511
            int row = idx >> 3;
            int k4  = (idx & 7) << 2;
            float4 v = make_float4(0.f, 0.f, 0.f, 0.f);
            if (m0 + row < NFLT)
                v = *reinterpret_cast<const float4*>(Ag + (size_t)(m0 + row) * CKD + k0 + k4);
            As[k4 + 0][row] = v.x;
            As[k4 + 1][row] = v.y;
            As[k4 + 2][row] = v.z;
            As[k4 + 3][row] = v.w;
        }
        // B tile 32x64: im2col on the fly
#pragma unroll
        for (int q = 0; q < 8; q++) {
            int idx = tid + q * 256;
            int kk = idx >> 6;
            int n  = idx & 63;
            int kg = k0 + kk;
            int c  = kg / 9;
            int r  = kg - c * 9;
            int ky = r / 3;
            int kx = r - ky * 3;
            int p = n0 + n;
            float v = 0.0f;
            if (p < PP) {
                int y = p / WW, x = p - (p / WW) * WW;
                int yy = y + ky - 1, xx = x + kx - 1;
                if (yy >= 0 && yy < HH && xx >= 0 && xx < WW)
                    v = Fg[(c * HH + yy) * WW + xx];
            }
            Bs[kk][n] = v;
        }
        __syncthreads();
#pragma unroll
        for (int kk = 0; kk < 32; kk++) {
            float4 a4 = *reinterpret_cast<const float4*>(&As[kk][ty << 2]);
            float4 b4 = *reinterpret_cast<const float4*>(&Bs[kk][tx << 2]);
            float av[4] = {a4.x, a4.y, a4.z, a4.w};
            float bv[4] = {b4.x, b4.y, b4.z, b4.w};
#pragma unroll
            for (int i = 0; i < 4; i++)
#pragma unroll
                for (int j = 0; j < 4; j++)
                    acc[i][j] = fmaf(av[i], bv[j], acc[i][j]);
        }
        __syncthreads();
    }

    if (MODE == 0) {
        // scores -> mapped residuals, weight-mask
#pragma unroll
        for (int i = 0; i < 4; i++) {
            int m = m0 + (ty << 2) + i;
            if (m >= NFLT) continue;
            int i0 = m / WW, i1 = m - i0 * WW;
            size_t base = ((size_t)s * NFLT + m) * PSTR;
#pragma unroll
            for (int j = 0; j < 4; j++) {
                int p = n0 + (tx << 2) + j;
                if (p >= PSTR) continue;
                if (p >= PP) {  // zero the 3 padding columns
                    g_resid[base + p] = 0.0f;
                    g_wm[base + p]    = 0.0f;
                    continue;
                }
                int j0 = p / WW, j1 = p - j0 * WW;
                int ia = 22 - i0 + j0, ib = 22 - i1 + j1;
                float lab = g_lbl[ia * DHW + ib];
                float sw  = g_sp[ia * DHW + ib];
                float sc = acc[i][j];
                float act, mask;
                if (m == p) {  // target-mask == 1 (BG_MASK_VAL = 0)
                    act = sc; mask = 1.0f;
                } else {
                    act  = fmaxf(sc, 0.0f);
                    mask = sc > 0.0f ? 1.0f : (sc < 0.0f ? 0.0f : 0.5f);
                }
                g_resid[base + p] = mask * sw * sw * (act - lab);
                g_wm[base + p]    = mask * sw;
            }
        }
    } else {
        // scores_grad -> weighted-square row sums into g_den
        float rp[4] = {0.f, 0.f, 0.f, 0.f};
#pragma unroll
        for (int i = 0; i < 4; i++) {
            int m = m0 + (ty << 2) + i;
            if (m >= NFLT) continue;
            size_t base = ((size_t)s * NFLT + m) * PSTR;
#pragma unroll
            for (int j = 0; j < 4; j++) {
                int p = n0 + (tx << 2) + j;
                if (p >= PP) continue;
                float w = g_wm[base + p];
                float v = w * acc[i][j];
                rp[i] += v * v;
            }
        }
        if (tid < 64) red[tid] = 0.0f;
        __syncthreads();
#pragma unroll
        for (int i = 0; i < 4; i++) atomicAdd(&red[(ty << 2) + i], rp[i]);
        __syncthreads();
        if (tid < 64 && m0 + tid < NFLT)
            atomicAdd(&g_den[s * NFLT + m0 + tid], red[tid]);
    }
}

// ---------------------------------------------------------------------------
// Weight-transpose conv as GEMM:
// grad[m=nf, n=(c,ky,kx)] = sum_p resid[m,p] * im2col(feat)[n,p]  (+ reg*f)
// grid: (36, 9, 8); same tiling. Epilogue also reduces alpha_num -> g_num.
// ---------------------------------------------------------------------------
__global__ __launch_bounds__(256) void k_bwd(const float* __restrict__ fsrc,
                                             const float* __restrict__ feat,
                                             const float* __restrict__ p_reg) {
    __shared__ float As[32][64];
    __shared__ float Bs[32][64];
    __shared__ float red[64];

    const int s  = blockIdx.z;
    const int m0 = blockIdx.y * 64;
    const int n0 = blockIdx.x * 64;
    const int tid = threadIdx.x;
    const int tx = tid & 15, ty = tid >> 4;

    const float* Ag = g_resid + (size_t)s * NFLT * PSTR;
    const float* Fg = feat    + (size_t)s * CC * HH * WW;

    float acc[4][4] = {};

    for (int k0 = 0; k0 < 544; k0 += 32) {  // K = 529, padded-row loads
#pragma unroll
        for (int q = 0; q < 2; q++) {
            int idx = tid + q * 256;
            int row = idx >> 3;
            int k4  = (idx & 7) << 2;
            float4 v = make_float4(0.f, 0.f, 0.f, 0.f);
            if (m0 + row < NFLT && k0 + k4 < PSTR)
                v = *reinterpret_cast<const float4*>(Ag + (size_t)(m0 + row) * PSTR + k0 + k4);
            As[k4 + 0][row] = v.x;
            As[k4 + 1][row] = v.y;
            As[k4 + 2][row] = v.z;
            As[k4 + 3][row] = v.w;
        }
#pragma unroll
        for (int q = 0; q < 8; q++) {
            int idx = tid + q * 256;
            int kk = idx >> 6;
            int n  = idx & 63;
            int p  = k0 + kk;
            float v = 0.0f;
            if (p < PP) {
                int y = p / WW, x = p - (p / WW) * WW;
                int ck = n0 + n;
                int c  = ck / 9;
                int r  = ck - c * 9;
                int ky = r / 3;
                int kx = r - ky * 3;
                int yy = y + ky - 1, xx = x + kx - 1;
                if (yy >= 0 && yy < HH && xx >= 0 && xx < WW)
                    v = Fg[(c * HH + yy) * WW + xx];
            }
            Bs[kk][n] = v;
        }
        __syncthreads();
#pragma unroll
        for (int kk = 0; kk < 32; kk++) {
            float4 a4 = *reinterpret_cast<const float4*>(&As[kk][ty << 2]);
            float4 b4 = *reinterpret_cast<const float4*>(&Bs[kk][tx << 2]);
            float av[4] = {a4.x, a4.y, a4.z, a4.w};
            float bv[4] = {b4.x, b4.y, b4.z, b4.w};
#pragma unroll
            for (int i = 0; i < 4; i++)
#pragma unroll
                for (int j = 0; j < 4; j++)
                    acc[i][j] = fmaf(av[i], bv[j], acc[i][j]);
        }
        __syncthreads();
    }

    float fr = p_reg[0];
    float regw = fmaxf(fr * fr, 1e-10f);  // max(filter_reg^2, MIN_FILTER_REG^2)
    float rp[4] = {0.f, 0.f, 0.f, 0.f};
#pragma unroll
    for (int i = 0; i < 4; i++) {
        int m = m0 + (ty << 2) + i;
        if (m >= NFLT) continue;
        size_t base = ((size_t)s * NFLT + m) * CKD + n0 + (tx << 2);
#pragma unroll
        for (int j = 0; j < 4; j++) {
            float g = acc[i][j] + regw * fsrc[base + j];
            g_grad[base + j] = g;
            rp[i] += g * g;
        }
    }
    if (tid < 64) red[tid] = 0.0f;
    __syncthreads();
#pragma unroll
    for (int i = 0; i < 4; i++) atomicAdd(&red[(ty << 2) + i], rp[i]);
    __syncthreads();
    if (tid < 64 && m0 + tid < NFLT)
        atomicAdd(&g_num[s * NFLT + m0 + tid], red[tid]);
}

// ---------------------------------------------------------------------------
// f_new = f - step * alpha(s,nf) * grad ; alpha = num / max(den + reg*num, 1e-8)
// ---------------------------------------------------------------------------
__global__ __launch_bounds__(256) void k_update(const float* __restrict__ fsrc,
                                                float* __restrict__ fdst,
                                                const float* __restrict__ p_step,
                                                const float* __restrict__ p_reg) {
    size_t i = (size_t)blockIdx.x * blockDim.x + threadIdx.x;
    const size_t total4 = (size_t)SS * NFLT * CKD / 4;
    if (i >= total4) return;
    size_t e0 = i * 4;
    int row = (int)(e0 / CKD);  // s*NFLT + nf (CKD % 4 == 0, so all 4 share a row)
    float num = g_num[row];
    float den = g_den[row];
    float fr = p_reg[0];
    float regw = fmaxf(fr * fr, 1e-10f);
    float denom = fmaxf(den + regw * num, 1e-8f);
    float alpha = num / denom;
    float sa = expf(p_step[0]) * alpha;
    float4 f4 = *reinterpret_cast<const float4*>(fsrc + e0);
    float4 g4 = *reinterpret_cast<const float4*>(&g_grad[e0]);
    float4 o;
    o.x = f4.x - sa * g4.x;
    o.y = f4.y - sa * g4.y;
    o.z = f4.z - sa * g4.z;
    o.w = f4.w - sa * g4.w;
    *reinterpret_cast<float4*>(fdst + e0) = o;
}

// ---------------------------------------------------------------------------
extern "C" void kernel_launch(void* const* d_in, const int* in_sizes, int n_in,
                              void* d_out, int out_size) {
    const float* fin   = (const float*)d_in[0];  // filter (S,NF,C,3,3)
    const float* feat  = (const float*)d_in[1];  // feat   (1,S,C,H,W)
    const float* wl    = (const float*)d_in[2];  // w_label (10)
    const float* ws    = (const float*)d_in[3];  // w_spatial (10)
    const float* pstep = (const float*)d_in[4];  // log_step_length ()
    const float* preg  = (const float*)d_in[5];  // filter_reg ()

    float *pf = nullptr, *pgrad = nullptr;
    cudaGetSymbolAddress((void**)&pf, g_f);
    cudaGetSymbolAddress((void**)&pgrad, g_grad);

    dim3 gfwd(9, 9, SS);
    dim3 gbwd(CKD / 64, 9, SS);
    int upd_blocks = (int)(((size_t)SS * NFLT * CKD / 4 + 255) / 256);

    k_tables<<<8, 256>>>(wl, ws);

    for (int it = 0; it < 2; ++it) {
        const float* fcur = (it == 0) ? fin : pf;
        float* fnext = (it == 0) ? pf : (float*)d_out;

        k_fwd<0><<<gfwd, 256>>>(fcur, feat);            // scores -> residuals, wm
        k_zero<<<17, 256>>>();                          // clear num/den
        k_bwd<<<gbwd, 256>>>(fcur, feat, preg);         // filter_grad + alpha_num
        k_fwd<1><<<gfwd, 256>>>(pgrad, feat);           // scores_grad -> alpha_den
        k_update<<<upd_blocks, 256>>>(fcur, fnext, pstep, preg);
    }
}

// round 3
// speedup vs baseline: 1.4977x; 1.4977x over previous
#include <cuda_runtime.h>
#include <math.h>

#define SS   8
#define CC   256
#define HH   23
#define WW   23
#define NFL  529
#define PP   529
#define PSTR 544            // padded K for the transpose GEMM (mult of 16)
#define CKD  2304           // C*3*3
#define DHW  45

// Device-global scratch (no allocation allowed)
__device__ float g_f[SS * NFL * CKD];
__device__ float g_grad[SS * NFL * CKD];
__device__ float g_resid[SS * NFL * PSTR];
__device__ float g_wm[SS * NFL * PSTR];
__device__ float g_col[SS * CKD * PSTR];   // im2col  [s][ck][p]  (B for grad GEMM)
__device__ float g_colT[(size_t)SS * PP * CKD];  // im2colT [s][p][ck] (B for fwd GEMMs)
__device__ float g_num[SS * NFL];
__device__ float g_den[SS * NFL];
__device__ float g_lbl[DHW * DHW];
__device__ float g_sp[DHW * DHW];

// ---------------------------------------------------------------------------
__global__ void k_tables(const float* __restrict__ wl, const float* __restrict__ ws) {
    int i = blockIdx.x * blockDim.x + threadIdx.x;
    if (i >= DHW * DHW) return;
    int a = i / DHW, b = i - a * DHW;
    float da = (float)a - 22.0f, db = (float)b - 22.0f;
    float t = sqrtf(da * da + db * db) * 2.0f;
    float lab = 0.0f, sp = 0.0f;
#pragma unroll
    for (int k = 0; k < 9; k++) {
        float v = fmaxf(0.0f, 1.0f - fabsf(t - (float)k));
        lab += wl[k] * v;
        sp  += ws[k] * v;
    }
    float v9 = fminf(fmaxf(t - 8.0f, 0.0f), 1.0f);
    lab += wl[9] * v9;
    sp  += ws[9] * v9;
    g_lbl[i] = lab;
    g_sp[i]  = sp;
}

__global__ void k_zero() {
    int i = blockIdx.x * blockDim.x + threadIdx.x;
    if (i < SS * NFL) { g_num[i] = 0.0f; g_den[i] = 0.0f; }
}

// Shared im2col index -> feat value
__device__ __forceinline__ float im2col_val(const float* __restrict__ feat,
                                            int s, int ck, int p) {
    int c = ck / 9, r = ck - c * 9;
    int ky = r / 3, kx = r - ky * 3;
    int y = p / WW, x = p - (p / WW) * WW;
    int yy = y + ky - 1, xx = x + kx - 1;
    if (yy < 0 || yy >= HH || xx < 0 || xx >= WW) return 0.0f;
    return feat[(((size_t)s * CC + c) * HH + yy) * WW + xx];
}

__global__ __launch_bounds__(256) void k_im2col(const float* __restrict__ feat) {
    size_t i = (size_t)blockIdx.x * 256 + threadIdx.x;
    const size_t total = (size_t)SS * CKD * PSTR;
    if (i >= total) return;
    int s  = (int)(i / ((size_t)CKD * PSTR));
    int r  = (int)(i - (size_t)s * CKD * PSTR);
    int ck = r / PSTR;
    int p  = r - ck * PSTR;
    g_col[i] = (p < PP) ? im2col_val(feat, s, ck, p) : 0.0f;
}

__global__ __launch_bounds__(256) void k_im2colT(const float* __restrict__ feat) {
    size_t i = (size_t)blockIdx.x * 256 + threadIdx.x;
    const size_t total = (size_t)SS * PP * CKD;
    if (i >= total) return;
    int s  = (int)(i / ((size_t)PP * CKD));
    int r  = (int)(i - (size_t)s * PP * CKD);
    int p  = r / CKD;
    int ck = r - p * CKD;
    g_colT[i] = im2col_val(feat, s, ck, p);
}

// ---------------------------------------------------------------------------
// TF32 helpers
// ---------------------------------------------------------------------------
__device__ __forceinline__ void split_tf32(float v, unsigned& hi, unsigned& lo) {
    unsigned h;
    asm("cvt.rna.tf32.f32 %0, %1;" : "=r"(h) : "f"(v));
    float rem = v - __uint_as_float(h);
    unsigned l;
    asm("cvt.rna.tf32.f32 %0, %1;" : "=r"(l) : "f"(rem));
    hi = h; lo = l;
}

__device__ __forceinline__ void mma8(float* d, const unsigned* a, const unsigned* b) {
    asm volatile(
        "mma.sync.aligned.m16n8k8.row.col.f32.tf32.tf32.f32 "
        "{%0,%1,%2,%3}, {%4,%5,%6,%7}, {%8,%9}, {%0,%1,%2,%3};"
        : "+f"(d[0]), "+f"(d[1]), "+f"(d[2]), "+f"(d[3])
        : "r"(a[0]), "r"(a[1]), "r"(a[2]), "r"(a[3]), "r"(b[0]), "r"(b[1]));
}

__device__ __forceinline__ void cp16(void* sdst, const void* gsrc, bool pred) {
    unsigned saddr = (unsigned)__cvta_generic_to_shared(sdst);
    int sz = pred ? 16 : 0;
    asm volatile("cp.async.cg.shared.global [%0], [%1], 16, %2;\n"
                 :: "r"(saddr), "l"(gsrc), "r"(sz));
}

// ---------------------------------------------------------------------------
// Unified GEMM: C[M x N] = A[M x K] * B^T (B stored [n][k], k-contiguous)
// MODE 0: A = filter,  B = g_colT, K=CKD, N=PP   -> residual epilogue
// MODE 1: A = g_grad,  B = g_colT, K=CKD, N=PP   -> alpha_den epilogue
// MODE 2: A = g_resid, B = g_col,  K=PSTR, N=CKD -> grad + alpha_num epilogue
// Block 128x128x16, 8 warps (2x4), warp tile 64x32, mma m16n8k8 tf32 x3 split
// ---------------------------------------------------------------------------
template <int MODE>
__global__ __launch_bounds__(256) void k_gemm(const float* __restrict__ Aext,
                                              const float* __restrict__ p_reg) {
    constexpr int K   = (MODE == 2) ? PSTR : CKD;
    constexpr int LDA = (MODE == 2) ? PSTR : CKD;
    constexpr int LDB = (MODE == 2) ? PSTR : CKD;
    constexpr int NBR = (MODE == 2) ? CKD : PP;   // valid B rows (n extent)
    constexpr int KT  = K / 16;

    const int s  = blockIdx.z;
    const int m0 = blockIdx.y * 128;
    const int n0 = blockIdx.x * 128;
    const int tid = threadIdx.x;

    const float* Ag =
        (MODE == 0) ? (Aext + (size_t)s * NFL * CKD)
      : (MODE == 1) ? (g_grad + (size_t)s * NFL * CKD)
                    : (g_resid + (size_t)s * NFL * PSTR);
    const float* Bg = (MODE == 2) ? (g_col + (size_t)s * CKD * PSTR)
                                  : (g_colT + (size_t)s * PP * CKD);

    __shared__ float As[2][128][20];
    __shared__ float Bs[2][128][20];

    const int w = tid >> 5, lane = tid & 31;
    const int g = lane >> 2, t = lane & 3;
    const int wm0 = (w >> 2) * 64, wn0 = (w & 3) * 32;

    float acc[4][4][4] = {};

    // tile loader (cp.async)
    auto load_tile = [&](int kt, int buf) {
        int k0 = kt * 16;
#pragma unroll
        for (int q = 0; q < 2; q++) {
            int id  = q * 256 + tid;
            int row = id >> 2;
            int c4  = (id & 3) << 2;
            bool pa = (m0 + row) < NFL;
            const float* sa = Ag + (size_t)(pa ? m0 + row : 0) * LDA + k0 + c4;
            cp16(&As[buf][row][c4], sa, pa);
            bool pb = (n0 + row) < NBR;
            const float* sb = Bg + (size_t)(pb ? n0 + row : 0) * LDB + k0 + c4;
            cp16(&Bs[buf][row][c4], sb, pb);
        }
        asm volatile("cp.async.commit_group;\n");
    };

    load_tile(0, 0);

    for (int kt = 0; kt < KT; kt++) {
        if (kt + 1 < KT) {
            load_tile(kt + 1, (kt + 1) & 1);
            asm volatile("cp.async.wait_group 1;\n");
        } else {
            asm volatile("cp.async.wait_group 0;\n");
        }
        __syncthreads();
        const int b = kt & 1;
#pragma unroll
        for (int ks = 0; ks < 16; ks += 8) {
            unsigned ah[4][4], al[4][4], bh[4][2], bl[4][2];
#pragma unroll
            for (int im = 0; im < 4; im++) {
                int r = wm0 + im * 16;
                split_tf32(As[b][r + g][ks + t],         ah[im][0], al[im][0]);
                split_tf32(As[b][r + g + 8][ks + t],     ah[im][1], al[im][1]);
                split_tf32(As[b][r + g][ks + t + 4],     ah[im][2], al[im][2]);
                split_tf32(As[b][r + g + 8][ks + t + 4], ah[im][3], al[im][3]);
            }
#pragma unroll
            for (int in = 0; in < 4; in++) {
                int c = wn0 + in * 8;
                split_tf32(Bs[b][c + g][ks + t],     bh[in][0], bl[in][0]);
                split_tf32(Bs[b][c + g][ks + t + 4], bh[in][1], bl[in][1]);
            }
#pragma unroll
            for (int im = 0; im < 4; im++)
#pragma unroll
                for (int in = 0; in < 4; in++) {
                    mma8(acc[im][in], al[im], bh[in]);
                    mma8(acc[im][in], ah[im], bl[in]);
                    mma8(acc[im][in], ah[im], bh[in]);
                }
        }
        __syncthreads();
    }

    // ---- epilogues ----
    if (MODE == 0) {
#pragma unroll
        for (int im = 0; im < 4; im++)
#pragma unroll
            for (int in = 0; in < 4; in++)
#pragma unroll
                for (int e = 0; e < 4; e++) {
                    int m = m0 + wm0 + im * 16 + g + ((e >> 1) << 3);
                    int p = n0 + wn0 + in * 8 + 2 * t + (e & 1);
                    if (m >= NFL || p >= PSTR) continue;
                    size_t off = ((size_t)s * NFL + m) * PSTR + p;
                    if (p >= PP) { g_resid[off] = 0.0f; g_wm[off] = 0.0f; continue; }
                    int i0 = m / WW, i1 = m - i0 * WW;
                    int j0 = p / WW, j1 = p - j0 * WW;
                    int tl = (22 - i0 + j0) * DHW + (22 - i1 + j1);
                    float lab = g_lbl[tl];
                    float sw  = g_sp[tl];
                    float sc = acc[im][in][e];
                    float act, mask;
                    if (m == p) { act = sc; mask = 1.0f; }
                    else {
                        act  = fmaxf(sc, 0.0f);
                        mask = sc > 0.0f ? 1.0f : (sc < 0.0f ? 0.0f : 0.5f);
                    }
                    g_resid[off] = mask * sw * sw * (act - lab);
                    g_wm[off]    = mask * sw;
                }
    } else if (MODE == 1) {
        float rs[4][2] = {};
#pragma unroll
        for (int im = 0; im < 4; im++)
#pragma unroll
            for (int in = 0; in < 4; in++)
#pragma unroll
                for (int e = 0; e < 4; e++) {
                    int m = m0 + wm0 + im * 16 + g + ((e >> 1) << 3);
                    int p = n0 + wn0 + in * 8 + 2 * t + (e & 1);
                    if (m >= NFL || p >= PP) continue;
                    float wmv = g_wm[((size_t)s * NFL + m) * PSTR + p];
                    float v = wmv * acc[im][in][e];
                    rs[im][e >> 1] += v * v;
                }
#pragma unroll
        for (int im = 0; im < 4; im++)
#pragma unroll
            for (int h = 0; h < 2; h++) {
                float sum = rs[im][h];
                sum += __shfl_xor_sync(0xffffffffu, sum, 1);
                sum += __shfl_xor_sync(0xffffffffu, sum, 2);
                if (t == 0) {
                    int m = m0 + wm0 + im * 16 + g + h * 8;
                    if (m < NFL) atomicAdd(&g_den[s * NFL + m], sum);
                }
            }
    } else {
        float fr = p_reg[0];
        float regw = fmaxf(fr * fr, 1e-10f);
        float rs[4][2] = {};
#pragma unroll
        for (int im = 0; im < 4; im++)
#pragma unroll
            for (int in = 0; in < 4; in++)
#pragma unroll
                for (int e = 0; e < 4; e++) {
                    int m  = m0 + wm0 + im * 16 + g + ((e >> 1) << 3);
                    int ck = n0 + wn0 + in * 8 + 2 * t + (e & 1);
                    if (m >= NFL) continue;
                    size_t off = ((size_t)s * NFL + m) * CKD + ck;
                    float gg = acc[im][in][e] + regw * Aext[off];
                    g_grad[off] = gg;
                    rs[im][e >> 1] += gg * gg;
                }
#pragma unroll
        for (int im = 0; im < 4; im++)
#pragma unroll
            for (int h = 0; h < 2; h++) {
                float sum = rs[im][h];
                sum += __shfl_xor_sync(0xffffffffu, sum, 1);
                sum += __shfl_xor_sync(0xffffffffu, sum, 2);
                if (t == 0) {
                    int m = m0 + wm0 + im * 16 + g + h * 8;
                    if (m < NFL) atomicAdd(&g_num[s * NFL + m], sum);
                }
            }
    }
}

// ---------------------------------------------------------------------------
__global__ __launch_bounds__(256) void k_update(const float* __restrict__ fsrc,
                                                float* __restrict__ fdst,
                                                const float* __restrict__ p_step,
                                                const float* __restrict__ p_reg) {
    size_t i = (size_t)blockIdx.x * blockDim.x + threadIdx.x;
    const size_t total4 = (size_t)SS * NFL * CKD / 4;
    if (i >= total4) return;
    size_t e0 = i * 4;
    int row = (int)(e0 / CKD);
    float num = g_num[row];
    float den = g_den[row];
    float fr = p_reg[0];
    float regw = fmaxf(fr * fr, 1e-10f);
    float denom = fmaxf(den + regw * num, 1e-8f);
    float alpha = num / denom;
    float sa = expf(p_step[0]) * alpha;
    float4 f4 = *reinterpret_cast<const float4*>(fsrc + e0);
    float4 g4 = *reinterpret_cast<const float4*>(&g_grad[e0]);
    float4 o;
    o.x = f4.x - sa * g4.x;
    o.y = f4.y - sa * g4.y;
    o.z = f4.z - sa * g4.z;
    o.w = f4.w - sa * g4.w;
    *reinterpret_cast<float4*>(fdst + e0) = o;
}

// ---------------------------------------------------------------------------
extern "C" void kernel_launch(void* const* d_in, const int* in_sizes, int n_in,
                              void* d_out, int out_size) {
    const float* fin   = (const float*)d_in[0];
    const float* feat  = (const float*)d_in[1];
    const float* wl    = (const float*)d_in[2];
    const float* ws    = (const float*)d_in[3];
    const float* pstep = (const float*)d_in[4];
    const float* preg  = (const float*)d_in[5];

    float* pf = nullptr;
    cudaGetSymbolAddress((void**)&pf, g_f);

    dim3 gfwd(5, 5, SS);            // N tiles, M tiles, S
    dim3 gbwd(CKD / 128, 5, SS);    // 18, 5, 8
    int upd_blocks = (int)(((size_t)SS * NFL * CKD / 4 + 255) / 256);
    int i2c_blocks  = (int)(((size_t)SS * CKD * PSTR + 255) / 256);
    int i2ct_blocks = (int)(((size_t)SS * PP * CKD + 255) / 256);

    k_tables<<<8, 256>>>(wl, ws);
    k_im2col<<<i2c_blocks, 256>>>(feat);
    k_im2colT<<<i2ct_blocks, 256>>>(feat);

    for (int it = 0; it < 2; ++it) {
        const float* fcur = (it == 0) ? fin : pf;
        float* fnext = (it == 0) ? pf : (float*)d_out;

        k_gemm<0><<<gfwd, 256>>>(fcur, preg);   // scores -> residuals, wm
        k_zero<<<17, 256>>>();
        k_gemm<2><<<gbwd, 256>>>(fcur, preg);   // grad + alpha_num
        k_gemm<1><<<gfwd, 256>>>(nullptr, preg);// scores_grad -> alpha_den
        k_update<<<upd_blocks, 256>>>(fcur, fnext, pstep, preg);
    }
}

// round 4
// speedup vs baseline: 2.2869x; 1.5270x over previous
#include <cuda_runtime.h>
#include <cuda_bf16.h>
#include <math.h>

#define SS   8
#define CC   256
#define HH   23
#define WW   23
#define NFL  529
#define PP   529
#define PSTR 544
#define CKD  2304
#define DHW  45
#define SST  40                 // smem row stride (bf16 elems), 80B, 16B-mult
#define TSZ  (128 * SST)        // elems per tile buffer
#define SMEM_BYTES (4 * 2 * TSZ * 2)   // 4 arrays x 2 bufs x bf16

// ---- device-global scratch ----
__device__ float g_f[SS * NFL * CKD];
__device__ float g_grad[SS * NFL * CKD];
__device__ float g_wm[SS * NFL * PSTR];
__device__ __nv_bfloat16 g_fh[SS * NFL * CKD],    g_fl[SS * NFL * CKD];
__device__ __nv_bfloat16 g_gh[SS * NFL * CKD],    g_gl[SS * NFL * CKD];
__device__ __nv_bfloat16 g_rh[SS * NFL * PSTR],   g_rl[SS * NFL * PSTR];
__device__ __nv_bfloat16 g_ch[SS * CKD * PSTR],   g_cl[SS * CKD * PSTR];   // im2col [ck][p]
__device__ __nv_bfloat16 g_th[(size_t)SS * PP * CKD], g_tl[(size_t)SS * PP * CKD]; // im2colT [p][ck]
__device__ float g_num[SS * NFL];
__device__ float g_den[SS * NFL];
__device__ float g_lbl[DHW * DHW];
__device__ float g_sp[DHW * DHW];

// ---------------------------------------------------------------------------
__device__ __forceinline__ void splitbf(float v, __nv_bfloat16& h, __nv_bfloat16& l) {
    h = __float2bfloat16(v);
    l = __float2bfloat16(v - __bfloat162float(h));
}

__global__ void k_tables(const float* __restrict__ wl, const float* __restrict__ ws) {
    int i = blockIdx.x * blockDim.x + threadIdx.x;
    if (i >= DHW * DHW) return;
    int a = i / DHW, b = i - a * DHW;
    float da = (float)a - 22.0f, db = (float)b - 22.0f;
    float t = sqrtf(da * da + db * db) * 2.0f;
    float lab = 0.0f, sp = 0.0f;
#pragma unroll
    for (int k = 0; k < 9; k++) {
        float v = fmaxf(0.0f, 1.0f - fabsf(t - (float)k));
        lab += wl[k] * v; sp += ws[k] * v;
    }
    float v9 = fminf(fmaxf(t - 8.0f, 0.0f), 1.0f);
    lab += wl[9] * v9; sp += ws[9] * v9;
    g_lbl[i] = lab; g_sp[i] = sp;
}

__global__ void k_zero() {
    int i = blockIdx.x * blockDim.x + threadIdx.x;
    if (i < SS * NFL) { g_num[i] = 0.0f; g_den[i] = 0.0f; }
}

__device__ __forceinline__ float im2col_val(const float* __restrict__ feat,
                                            int s, int ck, int p) {
    int c = ck / 9, r = ck - c * 9;
    int ky = r / 3, kx = r - ky * 3;
    int y = p / WW, x = p - (p / WW) * WW;
    int yy = y + ky - 1, xx = x + kx - 1;
    if (yy < 0 || yy >= HH || xx < 0 || xx >= WW) return 0.0f;
    return feat[(((size_t)s * CC + c) * HH + yy) * WW + xx];
}

__global__ __launch_bounds__(256) void k_im2col(const float* __restrict__ feat) {
    size_t i = (size_t)blockIdx.x * 256 + threadIdx.x;
    const size_t total = (size_t)SS * CKD * PSTR;
    if (i >= total) return;
    int s  = (int)(i / ((size_t)CKD * PSTR));
    int r  = (int)(i - (size_t)s * CKD * PSTR);
    int ck = r / PSTR;
    int p  = r - ck * PSTR;
    float v = (p < PP) ? im2col_val(feat, s, ck, p) : 0.0f;
    splitbf(v, g_ch[i], g_cl[i]);
}

__global__ __launch_bounds__(256) void k_im2colT(const float* __restrict__ feat) {
    size_t i = (size_t)blockIdx.x * 256 + threadIdx.x;
    const size_t total = (size_t)SS * PP * CKD;
    if (i >= total) return;
    int s  = (int)(i / ((size_t)PP * CKD));
    int r  = (int)(i - (size_t)s * PP * CKD);
    int p  = r / CKD;
    int ck = r - p * CKD;
    splitbf(im2col_val(feat, s, ck, p), g_th[i], g_tl[i]);
}

__global__ __launch_bounds__(256) void k_split(const float* __restrict__ src,
                                               __nv_bfloat16* __restrict__ h,
                                               __nv_bfloat16* __restrict__ l) {
    size_t i = (size_t)blockIdx.x * 256 + threadIdx.x;
    const size_t total = (size_t)SS * NFL * CKD;
    if (i >= total) return;
    splitbf(src[i], h[i], l[i]);
}

// ---------------------------------------------------------------------------
__device__ __forceinline__ void ldsm4(unsigned* r, unsigned addr) {
    asm volatile("ldmatrix.sync.aligned.m8n8.x4.shared.b16 {%0,%1,%2,%3}, [%4];"
                 : "=r"(r[0]), "=r"(r[1]), "=r"(r[2]), "=r"(r[3]) : "r"(addr));
}
__device__ __forceinline__ void ldsm2(unsigned* r, unsigned addr) {
    asm volatile("ldmatrix.sync.aligned.m8n8.x2.shared.b16 {%0,%1}, [%2];"
                 : "=r"(r[0]), "=r"(r[1]) : "r"(addr));
}
__device__ __forceinline__ void mmabf(float* d, const unsigned* a, const unsigned* b) {
    asm volatile(
        "mma.sync.aligned.m16n8k16.row.col.f32.bf16.bf16.f32 "
        "{%0,%1,%2,%3}, {%4,%5,%6,%7}, {%8,%9}, {%0,%1,%2,%3};"
        : "+f"(d[0]), "+f"(d[1]), "+f"(d[2]), "+f"(d[3])
        : "r"(a[0]), "r"(a[1]), "r"(a[2]), "r"(a[3]), "r"(b[0]), "r"(b[1]));
}
__device__ __forceinline__ void cp16(void* sdst, const void* gsrc, bool pred) {
    unsigned saddr = (unsigned)__cvta_generic_to_shared(sdst);
    int sz = pred ? 16 : 0;
    asm volatile("cp.async.cg.shared.global [%0], [%1], 16, %2;\n"
                 :: "r"(saddr), "l"(gsrc), "r"(sz));
}

// ---------------------------------------------------------------------------
// C[M x N] = A * B^T, A/B presplit bf16 (hi,lo), 3-term compensated mma.
// MODE 0: A=filter(h,l), B=colT, K=CKD, N=PP  -> residual epilogue
// MODE 1: A=grad(h,l),   B=colT, K=CKD, N=PP  -> alpha_den epilogue
// MODE 2: A=resid(h,l),  B=col,  K=PSTR,N=CKD -> grad + alpha_num epilogue
// Block 128x128, K-tile 32, 8 warps (2x4), warp tile 64x32.
// ---------------------------------------------------------------------------
template <int MODE>
__global__ __launch_bounds__(256) void k_gemm(const __nv_bfloat16* __restrict__ Ahg,
                                              const __nv_bfloat16* __restrict__ Alg,
                                              const float* __restrict__ fsrc,
                                              const float* __restrict__ p_reg) {
    constexpr int K   = (MODE == 2) ? PSTR : CKD;
    constexpr int LD  = (MODE == 2) ? PSTR : CKD;   // same for A and B here
    constexpr int NBR = (MODE == 2) ? CKD : PP;
    constexpr int KT  = K / 32;

    const int s  = blockIdx.z;
    const int m0 = blockIdx.y * 128;
    const int n0 = blockIdx.x * 128;
    const int tid = threadIdx.x;

    const __nv_bfloat16* Ah = Ahg + (size_t)s * NFL * LD;
    const __nv_bfloat16* Al = Alg + (size_t)s * NFL * LD;
    const __nv_bfloat16* Bh = (MODE == 2) ? (g_ch + (size_t)s * CKD * PSTR)
                                          : (g_th + (size_t)s * PP * CKD);
    const __nv_bfloat16* Bl = (MODE == 2) ? (g_cl + (size_t)s * CKD * PSTR)
                                          : (g_tl + (size_t)s * PP * CKD);

    extern __shared__ __nv_bfloat16 sm[];
    // arr: 0=Ah 1=Al 2=Bh 3=Bl ; offset elems = (arr*2+buf)*TSZ
    const unsigned sbase = (unsigned)__cvta_generic_to_shared(sm);

    const int w = tid >> 5, lane = tid & 31;
    const int g = lane >> 2, t = lane & 3;
    const int wm0 = (w >> 2) * 64, wn0 = (w & 3) * 32;

    float acc[4][4][4] = {};

    auto load_tile = [&](int kt, int buf) {
        int k0 = kt * 32;
#pragma unroll
        for (int q = 0; q < 2; q++) {
            int id  = q * 256 + tid;
            int row = id >> 2;
            int c8  = (id & 3) << 3;
            bool pa = (m0 + row) < NFL;
            size_t ga = (size_t)(pa ? m0 + row : 0) * LD + k0 + c8;
            cp16(&sm[(0 * 2 + buf) * TSZ + row * SST + c8], Ah + ga, pa);
            cp16(&sm[(1 * 2 + buf) * TSZ + row * SST + c8], Al + ga, pa);
            bool pb = (n0 + row) < NBR;
            size_t gb = (size_t)(pb ? n0 + row : 0) * LD + k0 + c8;
            cp16(&sm[(2 * 2 + buf) * TSZ + row * SST + c8], Bh + gb, pb);
            cp16(&sm[(3 * 2 + buf) * TSZ + row * SST + c8], Bl + gb, pb);
        }
        asm volatile("cp.async.commit_group;\n");
    };

    load_tile(0, 0);

    for (int kt = 0; kt < KT; kt++) {
        if (kt + 1 < KT) {
            load_tile(kt + 1, (kt + 1) & 1);
            asm volatile("cp.async.wait_group 1;\n");
        } else {
            asm volatile("cp.async.wait_group 0;\n");
        }
        __syncthreads();
        const int b = kt & 1;
#pragma unroll
        for (int ks = 0; ks < 32; ks += 16) {
            unsigned ah[4][4], al[4][4], bh[4][2], bl[4][2];
#pragma unroll
            for (int im = 0; im < 4; im++) {
                int r = wm0 + im * 16 + (lane & 7) + ((lane >> 3) & 1) * 8;
                int c = ks + (lane >> 4) * 8;
                ldsm4(ah[im], sbase + ((0 * 2 + b) * TSZ + r * SST + c) * 2);
                ldsm4(al[im], sbase + ((1 * 2 + b) * TSZ + r * SST + c) * 2);
            }
#pragma unroll
            for (int in = 0; in < 4; in++) {
                int r = wn0 + in * 8 + (lane & 7);
                int c = ks + ((lane >> 3) & 1) * 8;
                ldsm2(bh[in], sbase + ((2 * 2 + b) * TSZ + r * SST + c) * 2);
                ldsm2(bl[in], sbase + ((3 * 2 + b) * TSZ + r * SST + c) * 2);
            }
#pragma unroll
            for (int im = 0; im < 4; im++)
#pragma unroll
                for (int in = 0; in < 4; in++) {
                    mmabf(acc[im][in], al[im], bh[in]);
                    mmabf(acc[im][in], ah[im], bl[in]);
                    mmabf(acc[im][in], ah[im], bh[in]);
                }
        }
        __syncthreads();
    }

    // ---- epilogues ----
    if (MODE == 0) {
#pragma unroll
        for (int im = 0; im < 4; im++)
#pragma unroll
            for (int in = 0; in < 4; in++)
#pragma unroll
                for (int e = 0; e < 4; e++) {
                    int m = m0 + wm0 + im * 16 + g + ((e >> 1) << 3);
                    int p = n0 + wn0 + in * 8 + 2 * t + (e & 1);
                    if (m >= NFL || p >= PSTR) continue;
                    size_t off = ((size_t)s * NFL + m) * PSTR + p;
                    if (p >= PP) {
                        g_rh[off] = __float2bfloat16(0.0f);
                        g_rl[off] = __float2bfloat16(0.0f);
                        g_wm[off] = 0.0f;
                        continue;
                    }
                    int i0 = m / WW, i1 = m - i0 * WW;
                    int j0 = p / WW, j1 = p - j0 * WW;
                    int tl = (22 - i0 + j0) * DHW + (22 - i1 + j1);
                    float lab = g_lbl[tl];
                    float sw  = g_sp[tl];
                    float sc = acc[im][in][e];
                    float act, mask;
                    if (m == p) { act = sc; mask = 1.0f; }
                    else {
                        act  = fmaxf(sc, 0.0f);
                        mask = sc > 0.0f ? 1.0f : (sc < 0.0f ? 0.0f : 0.5f);
                    }
                    float rv = mask * sw * sw * (act - lab);
                    splitbf(rv, g_rh[off], g_rl[off]);
                    g_wm[off] = mask * sw;
                }
    } else if (MODE == 1) {
        float rs[4][2] = {};
#pragma unroll
        for (int im = 0; im < 4; im++)
#pragma unroll
            for (int in = 0; in < 4; in++)
#pragma unroll
                for (int e = 0; e < 4; e++) {
                    int m = m0 + wm0 + im * 16 + g + ((e >> 1) << 3);
                    int p = n0 + wn0 + in * 8 + 2 * t + (e & 1);
                    if (m >= NFL || p >= PP) continue;
                    float wmv = g_wm[((size_t)s * NFL + m) * PSTR + p];
                    float v = wmv * acc[im][in][e];
                    rs[im][e >> 1] += v * v;
                }
#pragma unroll
        for (int im = 0; im < 4; im++)
#pragma unroll
            for (int h = 0; h < 2; h++) {
                float sum = rs[im][h];
                sum += __shfl_xor_sync(0xffffffffu, sum, 1);
                sum += __shfl_xor_sync(0xffffffffu, sum, 2);
                if (t == 0) {
                    int m = m0 + wm0 + im * 16 + g + h * 8;
                    if (m < NFL) atomicAdd(&g_den[s * NFL + m], sum);
                }
            }
    } else {
        float fr = p_reg[0];
        float regw = fmaxf(fr * fr, 1e-10f);
        float rs[4][2] = {};
#pragma unroll
        for (int im = 0; im < 4; im++)
#pragma unroll
            for (int in = 0; in < 4; in++)
#pragma unroll
                for (int e = 0; e < 4; e++) {
                    int m  = m0 + wm0 + im * 16 + g + ((e >> 1) << 3);
                    int ck = n0 + wn0 + in * 8 + 2 * t + (e & 1);
                    if (m >= NFL) continue;
                    size_t off = ((size_t)s * NFL + m) * CKD + ck;
                    float gg = acc[im][in][e] + regw * fsrc[off];
                    g_grad[off] = gg;
                    splitbf(gg, g_gh[off], g_gl[off]);
                    rs[im][e >> 1] += gg * gg;
                }
#pragma unroll
        for (int im = 0; im < 4; im++)
#pragma unroll
            for (int h = 0; h < 2; h++) {
                float sum = rs[im][h];
                sum += __shfl_xor_sync(0xffffffffu, sum, 1);
                sum += __shfl_xor_sync(0xffffffffu, sum, 2);
                if (t == 0) {
                    int m = m0 + wm0 + im * 16 + g + h * 8;
                    if (m < NFL) atomicAdd(&g_num[s * NFL + m], sum);
                }
            }
    }
}

// ---------------------------------------------------------------------------
__global__ __launch_bounds__(256) void k_update(const float* __restrict__ fsrc,
                                                float* __restrict__ fdst,
                                                const float* __restrict__ p_step,
                                                const float* __restrict__ p_reg) {
    size_t i = (size_t)blockIdx.x * blockDim.x + threadIdx.x;
    const size_t total4 = (size_t)SS * NFL * CKD / 4;
    if (i >= total4) return;
    size_t e0 = i * 4;
    int row = (int)(e0 / CKD);
    float num = g_num[row];
    float den = g_den[row];
    float fr = p_reg[0];
    float regw = fmaxf(fr * fr, 1e-10f);
    float denom = fmaxf(den + regw * num, 1e-8f);
    float alpha = num / denom;
    float sa = expf(p_step[0]) * alpha;
    float4 f4 = *reinterpret_cast<const float4*>(fsrc + e0);
    float4 g4 = *reinterpret_cast<const float4*>(&g_grad[e0]);
    float4 o;
    o.x = f4.x - sa * g4.x;
    o.y = f4.y - sa * g4.y;
    o.z = f4.z - sa * g4.z;
    o.w = f4.w - sa * g4.w;
    *reinterpret_cast<float4*>(fdst + e0) = o;
}

// ---------------------------------------------------------------------------
extern "C" void kernel_launch(void* const* d_in, const int* in_sizes, int n_in,
                              void* d_out, int out_size) {
    const float* fin   = (const float*)d_in[0];
    const float* feat  = (const float*)d_in[1];
    const float* wl    = (const float*)d_in[2];
    const float* ws    = (const float*)d_in[3];
    const float* pstep = (const float*)d_in[4];
    const float* preg  = (const float*)d_in[5];

    float* pf = nullptr;
    cudaGetSymbolAddress((void**)&pf, g_f);
    __nv_bfloat16 *pfh = nullptr, *pfl = nullptr, *pgh = nullptr, *pgl = nullptr,
                  *prh = nullptr, *prl = nullptr;
    cudaGetSymbolAddress((void**)&pfh, g_fh);
    cudaGetSymbolAddress((void**)&pfl, g_fl);
    cudaGetSymbolAddress((void**)&pgh, g_gh);
    cudaGetSymbolAddress((void**)&pgl, g_gl);
    cudaGetSymbolAddress((void**)&prh, g_rh);
    cudaGetSymbolAddress((void**)&prl, g_rl);

    static bool attr_done = false;
    if (!attr_done) {
        cudaFuncSetAttribute(k_gemm<0>, cudaFuncAttributeMaxDynamicSharedMemorySize, SMEM_BYTES);
        cudaFuncSetAttribute(k_gemm<1>, cudaFuncAttributeMaxDynamicSharedMemorySize, SMEM_BYTES);
        cudaFuncSetAttribute(k_gemm<2>, cudaFuncAttributeMaxDynamicSharedMemorySize, SMEM_BYTES);
        attr_done = true;
    }

    dim3 gfwd(5, 5, SS);
    dim3 gbwd(CKD / 128, 5, SS);
    int upd_blocks = (int)(((size_t)SS * NFL * CKD / 4 + 255) / 256);
    int spl_blocks = (int)(((size_t)SS * NFL * CKD + 255) / 256);
    int i2c_blocks  = (int)(((size_t)SS * CKD * PSTR + 255) / 256);
    int i2ct_blocks = (int)(((size_t)SS * PP * CKD + 255) / 256);

    k_tables<<<8, 256>>>(wl, ws);
    k_im2col<<<i2c_blocks, 256>>>(feat);
    k_im2colT<<<i2ct_blocks, 256>>>(feat);

    for (int it = 0; it < 2; ++it) {
        const float* fcur = (it == 0) ? fin : pf;
        float* fnext = (it == 0) ? pf : (float*)d_out;

        k_split<<<spl_blocks, 256>>>(fcur, pfh, pfl);
        k_gemm<0><<<gfwd, 256, SMEM_BYTES>>>(pfh, pfl, nullptr, preg);  // scores -> resid
        k_zero<<<17, 256>>>();
        k_gemm<2><<<gbwd, 256, SMEM_BYTES>>>(prh, prl, fcur, preg);     // grad + num
        k_gemm<1><<<gfwd, 256, SMEM_BYTES>>>(pgh, pgl, nullptr, preg);  // den
        k_update<<<upd_blocks, 256>>>(fcur, fnext, pstep, preg);
    }
}

// round 6
// speedup vs baseline: 2.6915x; 1.1769x over previous
#include <cuda_runtime.h>
#include <cuda_bf16.h>
#include <math.h>
#include <stdint.h>

#define SS   8
#define CC   256
#define HH   23
#define WW   23
#define NFL  529
#define PP   529
#define PSTR 576            // padded K for transpose GEMM (multiple of 32)
#define CKD  2304
#define DHW  45

// GEMM tiling: block 128(M) x 64(N), K-tile 32, 4 warps (2x2), warp 64x32
#define BM   128
#define BN   64
#define BK   32
#define RSTR 80             // smem row stride bytes (32 bf16 = 64B + 16B pad)
#define ASZ  (BM * RSTR)    // 10240
#define BSZ  (BN * RSTR)    // 5120
#define STG  (2 * ASZ + 2 * BSZ)   // 30720 per stage
#define SMEMG (2 * STG)            // 61440

// ---- device-global scratch ----
__device__ float g_f[SS * NFL * CKD];
__device__ float g_grad[SS * NFL * CKD];
__device__ float g_wm[SS * NFL * PSTR];
__device__ __nv_bfloat16 g_fh[SS * NFL * CKD],  g_fl[SS * NFL * CKD];
__device__ __nv_bfloat16 g_gh[SS * NFL * CKD],  g_gl[SS * NFL * CKD];
__device__ __nv_bfloat16 g_rh[SS * NFL * PSTR], g_rl[SS * NFL * PSTR];
__device__ __nv_bfloat16 g_ch[SS * CKD * PSTR], g_cl[SS * CKD * PSTR];          // im2col  [ck][p]
__device__ __nv_bfloat16 g_th[(size_t)SS * PP * CKD], g_tl[(size_t)SS * PP * CKD]; // im2colT [p][ck]
__device__ float g_num[SS * NFL];
__device__ float g_den[SS * NFL];
__device__ float g_lbl[DHW * DHW];
__device__ float g_sp[DHW * DHW];

// ---------------------------------------------------------------------------
__device__ __forceinline__ void splitbf(float v, __nv_bfloat16& h, __nv_bfloat16& l) {
    h = __float2bfloat16(v);
    l = __float2bfloat16(v - __bfloat162float(h));
}

__global__ void k_tables(const float* __restrict__ wl, const float* __restrict__ ws) {
    int i = blockIdx.x * blockDim.x + threadIdx.x;
    if (i >= DHW * DHW) return;
    int a = i / DHW, b = i - a * DHW;
    float da = (float)a - 22.0f, db = (float)b - 22.0f;
    float t = sqrtf(da * da + db * db) * 2.0f;
    float lab = 0.0f, sp = 0.0f;
#pragma unroll
    for (int k = 0; k < 9; k++) {
        float v = fmaxf(0.0f, 1.0f - fabsf(t - (float)k));
        lab += wl[k] * v; sp += ws[k] * v;
    }
    float v9 = fminf(fmaxf(t - 8.0f, 0.0f), 1.0f);
    lab += wl[9] * v9; sp += ws[9] * v9;
    g_lbl[i] = lab; g_sp[i] = sp;
}

__global__ void k_zero() {
    int i = blockIdx.x * blockDim.x + threadIdx.x;
    if (i < SS * NFL) { g_num[i] = 0.0f; g_den[i] = 0.0f; }
}

__device__ __forceinline__ float im2col_val(const float* __restrict__ feat,
                                            int s, int ck, int p) {
    int c = ck / 9, r = ck - c * 9;
    int ky = r / 3, kx = r - ky * 3;
    int y = p / WW, x = p - (p / WW) * WW;
    int yy = y + ky - 1, xx = x + kx - 1;
    if (yy < 0 || yy >= HH || xx < 0 || xx >= WW) return 0.0f;
    return feat[(((size_t)s * CC + c) * HH + yy) * WW + xx];
}

__global__ __launch_bounds__(256) void k_im2col(const float* __restrict__ feat) {
    size_t i = (size_t)blockIdx.x * 256 + threadIdx.x;
    const size_t total = (size_t)SS * CKD * PSTR;
    if (i >= total) return;
    int s  = (int)(i / ((size_t)CKD * PSTR));
    int r  = (int)(i - (size_t)s * CKD * PSTR);
    int ck = r / PSTR;
    int p  = r - ck * PSTR;
    float v = (p < PP) ? im2col_val(feat, s, ck, p) : 0.0f;
    splitbf(v, g_ch[i], g_cl[i]);
}

__global__ __launch_bounds__(256) void k_im2colT(const float* __restrict__ feat) {
    size_t i = (size_t)blockIdx.x * 256 + threadIdx.x;
    const size_t total = (size_t)SS * PP * CKD;
    if (i >= total) return;
    int s  = (int)(i / ((size_t)PP * CKD));
    int r  = (int)(i - (size_t)s * PP * CKD);
    int p  = r / CKD;
    int ck = r - p * CKD;
    splitbf(im2col_val(feat, s, ck, p), g_th[i], g_tl[i]);
}

__global__ __launch_bounds__(256) void k_split(const float* __restrict__ src,
                                               __nv_bfloat16* __restrict__ h,
                                               __nv_bfloat16* __restrict__ l) {
    size_t i = (size_t)blockIdx.x * 256 + threadIdx.x;
    const size_t total = (size_t)SS * NFL * CKD;
    if (i >= total) return;
    splitbf(src[i], h[i], l[i]);
}

// ---------------------------------------------------------------------------
__device__ __forceinline__ void ldsm4(unsigned* r, unsigned addr) {
    asm volatile("ldmatrix.sync.aligned.m8n8.x4.shared.b16 {%0,%1,%2,%3}, [%4];"
                 : "=r"(r[0]), "=r"(r[1]), "=r"(r[2]), "=r"(r[3]) : "r"(addr));
}
__device__ __forceinline__ void mmabf(float* d, const unsigned* a, const unsigned* b) {
    asm volatile(
        "mma.sync.aligned.m16n8k16.row.col.f32.bf16.bf16.f32 "
        "{%0,%1,%2,%3}, {%4,%5,%6,%7}, {%8,%9}, {%0,%1,%2,%3};"
        : "+f"(d[0]), "+f"(d[1]), "+f"(d[2]), "+f"(d[3])
        : "r"(a[0]), "r"(a[1]), "r"(a[2]), "r"(a[3]), "r"(b[0]), "r"(b[1]));
}
__device__ __forceinline__ void cp16(unsigned sdst, const void* gsrc, bool pred) {
    int sz = pred ? 16 : 0;
    asm volatile("cp.async.cg.shared.global [%0], [%1], 16, %2;\n"
                 :: "r"(sdst), "l"(gsrc), "r"(sz));
}

// ---------------------------------------------------------------------------
// C[M x N] = A * B^T, A/B presplit bf16 (hi,lo), 3-term compensated mma.
// MODE 0: A=filter(h,l), B=colT, K=CKD, N=PP  -> residual epilogue
// MODE 1: A=grad(h,l),   B=colT, K=CKD, N=PP  -> alpha_den epilogue
// MODE 2: A=resid(h,l),  B=col,  K=PSTR,N=CKD -> grad + alpha_num epilogue
// ---------------------------------------------------------------------------
template <int MODE>
__global__ __launch_bounds__(128, 3) void k_gemm(const __nv_bfloat16* __restrict__ Ahg,
                                                 const __nv_bfloat16* __restrict__ Alg,
                                                 const float* __restrict__ fsrc,
                                                 const float* __restrict__ p_reg) {
    constexpr int K   = (MODE == 2) ? PSTR : CKD;
    constexpr int LD  = K;
    constexpr int NBR = (MODE == 2) ? CKD : PP;
    constexpr int KT  = K / BK;              // 72 or 18

    const int s  = blockIdx.z;
    const int m0 = blockIdx.y * BM;
    const int n0 = blockIdx.x * BN;
    const int tid = threadIdx.x;
    const int w = tid >> 5, lane = tid & 31;
    const int g = lane >> 2, t = lane & 3;
    const int wm0 = (w >> 1) * 64;           // warp M offset (0/64)
    const int wn0 = (w & 1) * 32;            // warp N offset (0/32)

    const __nv_bfloat16* Ah = Ahg + (size_t)s * NFL * LD;
    const __nv_bfloat16* Al = Alg + (size_t)s * NFL * LD;
    const __nv_bfloat16* Bh = (MODE == 2) ? (g_ch + (size_t)s * CKD * PSTR)
                                          : (g_th + (size_t)s * PP * CKD);
    const __nv_bfloat16* Bl = (MODE == 2) ? (g_cl + (size_t)s * CKD * PSTR)
                                          : (g_tl + (size_t)s * PP * CKD);

    extern __shared__ char dsm[];
    const unsigned sb0 = (unsigned)__cvta_generic_to_shared(dsm);
    // stage layout: [Ah ASZ][Al ASZ][Bh BSZ][Bl BSZ]

    float acc[4][4][4] = {};

    auto load_stage = [&](int kt, int buf) {
        const unsigned st = sb0 + buf * STG;
        const int k0 = kt * BK;
        // A arrays: 512 chunks of 16B each -> 4 per thread per array
#pragma unroll
        for (int arr = 0; arr < 2; arr++) {
            const __nv_bfloat16* G = arr ? Al : Ah;
            const unsigned tb = st + arr * ASZ;
#pragma unroll
            for (int q = 0; q < 4; q++) {
                int ch  = q * 128 + tid;
                int row = ch >> 2, c16 = ch & 3;
                bool pr = (m0 + row) < NFL;
                const void* src = G + (size_t)(pr ? m0 + row : 0) * LD + k0 + c16 * 8;
                cp16(tb + row * RSTR + c16 * 16, src, pr);
            }
        }
        // B arrays: 256 chunks -> 2 per thread per array
#pragma unroll
        for (int arr = 0; arr < 2; arr++) {
            const __nv_bfloat16* G = arr ? Bl : Bh;
            const unsigned tb = st + 2 * ASZ + arr * BSZ;
#pragma unroll
            for (int q = 0; q < 2; q++) {
                int ch  = q * 128 + tid;
                int row = ch >> 2, c16 = ch & 3;
                bool pr = (n0 + row) < NBR;
                const void* src = G + (size_t)(pr ? n0 + row : 0) * LD + k0 + c16 * 8;
                cp16(tb + row * RSTR + c16 * 16, src, pr);
            }
        }
        asm volatile("cp.async.commit_group;\n");
    };

    load_stage(0, 0);
    if (KT > 1) load_stage(1, 1);

    for (int kt = 0; kt < KT; kt++) {
        if (kt + 1 < KT)
            asm volatile("cp.async.wait_group 1;\n");
        else
            asm volatile("cp.async.wait_group 0;\n");
        __syncthreads();
        const unsigned st = sb0 + (kt & 1) * STG;

#pragma unroll
        for (int ks = 0; ks < BK; ks += 16) {
            unsigned ah[4][4], al[4][4], bh[4][2], bl[4][2];
            // A fragments: 16x16 per ldsm4
            {
                int r = (lane & 7) + ((lane >> 3) & 1) * 8;
                int c = ks + (lane >> 4) * 8;
                unsigned off = (unsigned)((wm0 + r) * RSTR + c * 2);
#pragma unroll
                for (int im = 0; im < 4; im++) {
                    ldsm4(ah[im], st + off + im * 16 * RSTR);
                    ldsm4(al[im], st + ASZ + off + im * 16 * RSTR);
                }
            }
            // B fragments: 16 rows x 16 cols per ldsm4 -> two n-blocks
            {
                int q = lane >> 3;
                int r = (lane & 7) + (q >> 1) * 8;
                int c = ks + (q & 1) * 8;
                unsigned off = (unsigned)((wn0 + r) * RSTR + c * 2);
#pragma unroll
                for (int inp = 0; inp < 2; inp++) {
                    unsigned rv[4];
                    ldsm4(rv, st + 2 * ASZ + off + inp * 16 * RSTR);
                    bh[inp * 2][0] = rv[0]; bh[inp * 2][1] = rv[1];
                    bh[inp * 2 + 1][0] = rv[2]; bh[inp * 2 + 1][1] = rv[3];
                    ldsm4(rv, st + 2 * ASZ + BSZ + off + inp * 16 * RSTR);
                    bl[inp * 2][0] = rv[0]; bl[inp * 2][1] = rv[1];
                    bl[inp * 2 + 1][0] = rv[2]; bl[inp * 2 + 1][1] = rv[3];
                }
            }
#pragma unroll
            for (int im = 0; im < 4; im++)
#pragma unroll
                for (int in = 0; in < 4; in++) {
                    mmabf(acc[im][in], al[im], bh[in]);
                    mmabf(acc[im][in], ah[im], bl[in]);
                    mmabf(acc[im][in], ah[im], bh[in]);
                }
        }
        __syncthreads();
        if (kt + 2 < KT) load_stage(kt + 2, kt & 1);
    }

    // ---- epilogues ----
    if (MODE == 0) {
#pragma unroll
        for (int im = 0; im < 4; im++)
#pragma unroll
            for (int in = 0; in < 4; in++)
#pragma unroll
                for (int e = 0; e < 4; e++) {
                    int m = m0 + wm0 + im * 16 + g + ((e >> 1) << 3);
                    int p = n0 + wn0 + in * 8 + 2 * t + (e & 1);
                    if (m >= NFL || p >= PSTR) continue;
                    size_t off = ((size_t)s * NFL + m) * PSTR + p;
                    if (p >= PP) {
                        g_rh[off] = __float2bfloat16(0.0f);
                        g_rl[off] = __float2bfloat16(0.0f);
                        g_wm[off] = 0.0f;
                        continue;
                    }
                    int i0 = m / WW, i1 = m - i0 * WW;
                    int j0 = p / WW, j1 = p - j0 * WW;
                    int tl = (22 - i0 + j0) * DHW + (22 - i1 + j1);
                    float lab = g_lbl[tl];
                    float sw  = g_sp[tl];
                    float sc = acc[im][in][e];
                    float act, mask;
                    if (m == p) { act = sc; mask = 1.0f; }
                    else {
                        act  = fmaxf(sc, 0.0f);
                        mask = sc > 0.0f ? 1.0f : (sc < 0.0f ? 0.0f : 0.5f);
                    }
                    float rv = mask * sw * sw * (act - lab);
                    splitbf(rv, g_rh[off], g_rl[off]);
                    g_wm[off] = mask * sw;
                }
    } else if (MODE == 1) {
        float rs[4][2] = {};
#pragma unroll
        for (int im = 0; im < 4; im++)
#pragma unroll
            for (int in = 0; in < 4; in++)
#pragma unroll
                for (int e = 0; e < 4; e++) {
                    int m = m0 + wm0 + im * 16 + g + ((e >> 1) << 3);
                    int p = n0 + wn0 + in * 8 + 2 * t + (e & 1);
                    if (m >= NFL || p >= PP) continue;
                    float wmv = g_wm[((size_t)s * NFL + m) * PSTR + p];
                    float v = wmv * acc[im][in][e];
                    rs[im][e >> 1] += v * v;
                }
#pragma unroll
        for (int im = 0; im < 4; im++)
#pragma unroll
            for (int h = 0; h < 2; h++) {
                float sum = rs[im][h];
                sum += __shfl_xor_sync(0xffffffffu, sum, 1);
                sum += __shfl_xor_sync(0xffffffffu, sum, 2);
                if (t == 0) {
                    int m = m0 + wm0 + im * 16 + g + h * 8;
                    if (m < NFL) atomicAdd(&g_den[s * NFL + m], sum);
                }
            }
    } else {
        float fr = p_reg[0];
        float regw = fmaxf(fr * fr, 1e-10f);
        float rs[4][2] = {};
#pragma unroll
        for (int im = 0; im < 4; im++)
#pragma unroll
            for (int in = 0; in < 4; in++)
#pragma unroll
                for (int e = 0; e < 4; e++) {
                    int m  = m0 + wm0 + im * 16 + g + ((e >> 1) << 3);
                    int ck = n0 + wn0 + in * 8 + 2 * t + (e & 1);
                    if (m >= NFL) continue;
                    size_t off = ((size_t)s * NFL + m) * CKD + ck;
                    float gg = acc[im][in][e] + regw * fsrc[off];
                    g_grad[off] = gg;
                    splitbf(gg, g_gh[off], g_gl[off]);
                    rs[im][e >> 1] += gg * gg;
                }
#pragma unroll
        for (int im = 0; im < 4; im++)
#pragma unroll
            for (int h = 0; h < 2; h++) {
                float sum = rs[im][h];
                sum += __shfl_xor_sync(0xffffffffu, sum, 1);
                sum += __shfl_xor_sync(0xffffffffu, sum, 2);
                if (t == 0) {
                    int m = m0 + wm0 + im * 16 + g + h * 8;
                    if (m < NFL) atomicAdd(&g_num[s * NFL + m], sum);
                }
            }
    }
}

// ---------------------------------------------------------------------------
__global__ __launch_bounds__(256) void k_update(const float* __restrict__ fsrc,
                                                float* __restrict__ fdst,
                                                __nv_bfloat16* __restrict__ fh,
                                                __nv_bfloat16* __restrict__ fl,
                                                const float* __restrict__ p_step,
                                                const float* __restrict__ p_reg) {
    size_t i = (size_t)blockIdx.x * blockDim.x + threadIdx.x;
    const size_t total4 = (size_t)SS * NFL * CKD / 4;
    if (i >= total4) return;
    size_t e0 = i * 4;
    int row = (int)(e0 / CKD);
    float num = g_num[row];
    float den = g_den[row];
    float fr = p_reg[0];
    float regw = fmaxf(fr * fr, 1e-10f);
    float denom = fmaxf(den + regw * num, 1e-8f);
    float alpha = num / denom;
    float sa = expf(p_step[0]) * alpha;
    float4 f4 = *reinterpret_cast<const float4*>(fsrc + e0);
    float4 g4 = *reinterpret_cast<const float4*>(&g_grad[e0]);
    float4 o;
    o.x = f4.x - sa * g4.x;
    o.y = f4.y - sa * g4.y;
    o.z = f4.z - sa * g4.z;
    o.w = f4.w - sa * g4.w;
    *reinterpret_cast<float4*>(fdst + e0) = o;
    splitbf(o.x, fh[e0 + 0], fl[e0 + 0]);
    splitbf(o.y, fh[e0 + 1], fl[e0 + 1]);
    splitbf(o.z, fh[e0 + 2], fl[e0 + 2]);
    splitbf(o.w, fh[e0 + 3], fl[e0 + 3]);
}

// ---------------------------------------------------------------------------
extern "C" void kernel_launch(void* const* d_in, const int* in_sizes, int n_in,
                              void* d_out, int out_size) {
    const float* fin   = (const float*)d_in[0];
    const float* feat  = (const float*)d_in[1];
    const float* wl    = (const float*)d_in[2];
    const float* ws    = (const float*)d_in[3];
    const float* pstep = (const float*)d_in[4];
    const float* preg  = (const float*)d_in[5];

    float* pf = nullptr;
    cudaGetSymbolAddress((void**)&pf, g_f);
    __nv_bfloat16 *pfh = nullptr, *pfl = nullptr, *pgh = nullptr, *pgl = nullptr,
                  *prh = nullptr, *prl = nullptr;
    cudaGetSymbolAddress((void**)&pfh, g_fh);
    cudaGetSymbolAddress((void**)&pfl, g_fl);
    cudaGetSymbolAddress((void**)&pgh, g_gh);
    cudaGetSymbolAddress((void**)&pgl, g_gl);
    cudaGetSymbolAddress((void**)&prh, g_rh);
    cudaGetSymbolAddress((void**)&prl, g_rl);

    static bool attr_done = false;
    if (!attr_done) {
        cudaFuncSetAttribute(k_gemm<0>, cudaFuncAttributeMaxDynamicSharedMemorySize, SMEMG);
        cudaFuncSetAttribute(k_gemm<1>, cudaFuncAttributeMaxDynamicSharedMemorySize, SMEMG);
        cudaFuncSetAttribute(k_gemm<2>, cudaFuncAttributeMaxDynamicSharedMemorySize, SMEMG);
        attr_done = true;
    }

    dim3 gfwd(PSTR / BN, 5, SS);        // (9, 5, 8)
    dim3 gbwd(CKD / BN, 5, SS);         // (36, 5, 8)
    int upd_blocks = (int)(((size_t)SS * NFL * CKD / 4 + 255) / 256);
    int spl_blocks = (int)(((size_t)SS * NFL * CKD + 255) / 256);
    int i2c_blocks  = (int)(((size_t)SS * CKD * PSTR + 255) / 256);
    int i2ct_blocks = (int)(((size_t)SS * PP * CKD + 255) / 256);

    k_tables<<<8, 256>>>(wl, ws);
    k_im2col<<<i2c_blocks, 256>>>(feat);
    k_im2colT<<<i2ct_blocks, 256>>>(feat);
    k_split<<<spl_blocks, 256>>>(fin, pfh, pfl);

    for (int it = 0; it < 2; ++it) {
        const float* fcur = (it == 0) ? fin : pf;
        float* fnext = (it == 0) ? pf : (float*)d_out;

        k_gemm<0><<<gfwd, 128, SMEMG>>>(pfh, pfl, nullptr, preg);  // scores -> resid
        k_zero<<<17, 256>>>();
        k_gemm<2><<<gbwd, 128, SMEMG>>>(prh, prl, fcur, preg);     // grad + num
        k_gemm<1><<<gfwd, 128, SMEMG>>>(pgh, pgl, nullptr, preg);  // den
        k_update<<<upd_blocks, 256>>>(fcur, fnext, pfh, pfl, pstep, preg);
    }
}